// round 11
// baseline (speedup 1.0000x reference)
#include <cuda_runtime.h>
#include <cuda_bf16.h>
#include <math.h>

// Problem constants
#define NN     8192
#define IN_F   256
#define OUT_F  128
#define ALPHA  0.2f

#define ADJ_WORDS_PER_ROW (NN / 32)   // 256
#define MAXDEG 128

// Scratch (device globals; no allocation)
__device__ unsigned g_adj[NN * ADJ_WORDS_PER_ROW];   // 8 MB bitmask (dedup + fallback)
__device__ int      g_deg[NN];                       // deduped degree
__device__ int      g_nbr[NN * MAXDEG];              // neighbor lists (4 MB)
__device__ float    g_Wh[NN * OUT_F];                // 4 MB
__device__ float    g_s1[NN];
__device__ float    g_s2[NN];

// ---- f32x2 helpers (FFMA2 is PTX-only; ptxas never auto-fuses) -------------
__device__ __forceinline__ unsigned long long pk2(float lo, float hi) {
    unsigned long long r;
    asm("mov.b64 %0, {%1, %2};" : "=l"(r) : "f"(lo), "f"(hi));
    return r;
}
__device__ __forceinline__ void upk2(unsigned long long v, float& lo, float& hi) {
    asm("mov.b64 {%0, %1}, %2;" : "=f"(lo), "=f"(hi) : "l"(v));
}
#define FMA2(acc, a, b) \
    asm("fma.rn.f32x2 %0, %1, %2, %0;" : "+l"(acc) : "l"(a), "l"(b))

// ---------------------------------------------------------------------------
// Kernel 1: zero adjacency bitmask + degree array
// ---------------------------------------------------------------------------
__global__ __launch_bounds__(256) void zero_adj_kernel() {
    int idx = blockIdx.x * blockDim.x + threadIdx.x;      // uint4 index
    const int total = (NN * ADJ_WORDS_PER_ROW) / 4;       // 524288
    if (idx < total) {
        ((uint4*)g_adj)[idx] = make_uint4(0u, 0u, 0u, 0u);
    }
    if (idx < NN) g_deg[idx] = 0;
}

// ---------------------------------------------------------------------------
// Kernel 2: scatter edges; bitmask atomicOr dedups, unique edges appended.
// ---------------------------------------------------------------------------
__global__ __launch_bounds__(256) void scatter_kernel(const int* __restrict__ edge_index,
                                                      int E) {
    int k = blockIdx.x * blockDim.x + threadIdx.x;
    if (k < E) {
        int src = edge_index[k]     & (NN - 1);
        int dst = edge_index[E + k] & (NN - 1);
        unsigned bit = 1u << (dst & 31);
        unsigned old = atomicOr(&g_adj[src * ADJ_WORDS_PER_ROW + (dst >> 5)], bit);
        if (!(old & bit)) {
            int pos = atomicAdd(&g_deg[src], 1);
            if (pos < MAXDEG) g_nbr[src * MAXDEG + pos] = dst;
        }
    }
}

// ---------------------------------------------------------------------------
// Kernel 3: Wh = h @ W^T + b_lin (fused s1/s2), f32x2 FFMA2 mainloop.
// BM=32 rows/block, 256 blocks (~2/SM). Warp tr owns rows [tr*4, tr*4+4),
// lane owns cols [lane*4, lane*4+4). Accumulators are row-pairs (f32x2).
// B tile stored DUPLICATED in smem: ws2[k][chunk][lane] is a float4 holding
// (b,b,b',b') so the mainloop reads (b,b) pairs directly, conflict-free.
// ---------------------------------------------------------------------------
__global__ __launch_bounds__(256) void gemm_s_kernel(const float* __restrict__ h,
                                                     const float* __restrict__ W,
                                                     const float* __restrict__ b_lin,
                                                     const float* __restrict__ a) {
    const int BM = 32, BK = 32;
    __shared__ float hs[BK][BM];              // 4 KB  : hs[k][m]
    __shared__ float ws2[BK][2][32][4];       // 32 KB : duplicated B pairs

    int row0 = blockIdx.x * BM;
    int tid  = threadIdx.x;
    int tr   = tid >> 5;   // warp id 0..7 -> rows tr*4..tr*4+3
    int tc   = tid & 31;   // lane -> cols tc*4..tc*4+3

    // h-load coords (1 float4/thread): 32x32 floats
    int hm = tid >> 3, hk = tid & 7;

    unsigned long long acc[2][4];   // [row-pair][col] ; pair r = rows (2r, 2r+1)
#pragma unroll
    for (int r = 0; r < 2; r++)
#pragma unroll
        for (int c = 0; c < 4; c++) acc[r][c] = 0ull;

    for (int k0 = 0; k0 < IN_F; k0 += BK) {
        // --- load h tile ---
        {
            float4 v = *(const float4*)&h[(row0 + hm) * IN_F + k0 + hk * 4];
            hs[hk * 4 + 0][hm] = v.x;
            hs[hk * 4 + 1][hm] = v.y;
            hs[hk * 4 + 2][hm] = v.z;
            hs[hk * 4 + 3][hm] = v.w;
        }
        // --- load W tile, store duplicated pairs ---
#pragma unroll
        for (int l = 0; l < 4; l++) {
            int idx = tid + 256 * l;
            int n   = idx >> 3;          // 0..127
            int kq  = idx & 7;
            float4 v = *(const float4*)&W[n * IN_F + k0 + kq * 4];
            int lane_d = n >> 2;
            int c      = (n >> 1) & 1;
            int half   = (n & 1) * 2;
            float vv[4] = {v.x, v.y, v.z, v.w};
#pragma unroll
            for (int i = 0; i < 4; i++) {
                int k = kq * 4 + i;
                ws2[k][c][lane_d][half + 0] = vv[i];
                ws2[k][c][lane_d][half + 1] = vv[i];
            }
        }
        __syncthreads();

#pragma unroll
        for (int k = 0; k < BK; k++) {
            float4 ha = *(const float4*)&hs[k][tr * 4];          // broadcast
            unsigned long long ap0 = pk2(ha.x, ha.y);            // rows (0,1)
            unsigned long long ap1 = pk2(ha.z, ha.w);            // rows (2,3)
            // b pairs: chunk0 = (b0,b0,b1,b1), chunk1 = (b2,b2,b3,b3)
            const unsigned long long* bp0 = (const unsigned long long*)&ws2[k][0][tc][0];
            const unsigned long long* bp1 = (const unsigned long long*)&ws2[k][1][tc][0];
            unsigned long long b0 = bp0[0], b1 = bp0[1];
            unsigned long long b2 = bp1[0], b3 = bp1[1];
            FMA2(acc[0][0], ap0, b0);  FMA2(acc[1][0], ap1, b0);
            FMA2(acc[0][1], ap0, b1);  FMA2(acc[1][1], ap1, b1);
            FMA2(acc[0][2], ap0, b2);  FMA2(acc[1][2], ap1, b2);
            FMA2(acc[0][3], ap0, b3);  FMA2(acc[1][3], ap1, b3);
        }
        __syncthreads();
    }

    // unpack accumulators: rows tr*4 + i, cols tc*4 + c
    float av[4][4];
#pragma unroll
    for (int r = 0; r < 2; r++)
#pragma unroll
        for (int c = 0; c < 4; c++)
            upk2(acc[r][c], av[2 * r][c], av[2 * r + 1][c]);

    int col = tc * 4;
    float4 blv = *(const float4*)&b_lin[col];
    float4 a1v = *(const float4*)&a[col];
    float4 a2v = *(const float4*)&a[OUT_F + col];
    float bl[4]  = {blv.x, blv.y, blv.z, blv.w};
    float a1r[4] = {a1v.x, a1v.y, a1v.z, a1v.w};
    float a2r[4] = {a2v.x, a2v.y, a2v.z, a2v.w};

#pragma unroll
    for (int i = 0; i < 4; i++) {
        int row = row0 + tr * 4 + i;
        float v0 = av[i][0] + bl[0];
        float v1 = av[i][1] + bl[1];
        float v2 = av[i][2] + bl[2];
        float v3 = av[i][3] + bl[3];
        *(float4*)&g_Wh[row * OUT_F + col] = make_float4(v0, v1, v2, v3);
        float p1 = v0 * a1r[0] + v1 * a1r[1] + v2 * a1r[2] + v3 * a1r[3];
        float p2 = v0 * a2r[0] + v1 * a2r[1] + v2 * a2r[2] + v3 * a2r[3];
#pragma unroll
        for (int o = 16; o > 0; o >>= 1) {
            p1 += __shfl_xor_sync(0xffffffffu, p1, o);
            p2 += __shfl_xor_sync(0xffffffffu, p2, o);
        }
        if (tc == 0) {
            g_s1[row] = p1;
            g_s2[row] = p2;
        }
    }
}

// ---------------------------------------------------------------------------
// Kernel 4: warp-per-row softmax + aggregation + ELU (8-deep gather unroll)
// ---------------------------------------------------------------------------
__device__ __forceinline__ float elu1(float v) {
    return (v > 0.0f) ? v : expm1f(v);
}

__global__ __launch_bounds__(256) void attn_kernel(const float* __restrict__ b_att_p,
                                                   float* __restrict__ out) {
    __shared__ int   sj[8][MAXDEG];
    __shared__ float sw[8][MAXDEG];

    const unsigned FULL = 0xffffffffu;
    int lane = threadIdx.x & 31;
    int wrp  = threadIdx.x >> 5;
    int i    = blockIdx.x * 8 + wrp;

    float batt = *b_att_p;
    float s1i  = g_s1[i];
    int   deg  = g_deg[i];
    int   col  = lane * 4;

    if (deg > 0 && deg <= MAXDEG) {
        const int* nbr = &g_nbr[i * MAXDEG];

        int   jarr[4];
        float earr[4];
        float lmax = -INFINITY;
#pragma unroll
        for (int c = 0; c < 4; c++) {
            int k = c * 32 + lane;
            if (k < deg) {
                int j = nbr[k];
                float t = s1i + g_s2[j] + batt;
                float e = (t > 0.0f) ? t : ALPHA * t;
                jarr[c] = j;
                earr[c] = e;
                lmax = fmaxf(lmax, e);
            }
        }
#pragma unroll
        for (int o = 16; o > 0; o >>= 1)
            lmax = fmaxf(lmax, __shfl_xor_sync(FULL, lmax, o));

        float ls = 0.0f;
#pragma unroll
        for (int c = 0; c < 4; c++) {
            int k = c * 32 + lane;
            if (k < deg) {
                float w = __expf(earr[c] - lmax);
                sj[wrp][k] = jarr[c];
                sw[wrp][k] = w;
                ls += w;
            }
        }
#pragma unroll
        for (int o = 16; o > 0; o >>= 1)
            ls += __shfl_xor_sync(FULL, ls, o);
        __syncwarp();

        // aggregation: 8 gathers in flight
        float4 acc = make_float4(0.f, 0.f, 0.f, 0.f);
        int k = 0;
        for (; k + 8 <= deg; k += 8) {
            float4 v[8];
            float  w[8];
#pragma unroll
            for (int u = 0; u < 8; u++) {
                int j = sj[wrp][k + u];
                w[u]  = sw[wrp][k + u];
                v[u]  = *(const float4*)&g_Wh[j * OUT_F + col];
            }
#pragma unroll
            for (int u = 0; u < 8; u++) {
                acc.x = fmaf(w[u], v[u].x, acc.x);
                acc.y = fmaf(w[u], v[u].y, acc.y);
                acc.z = fmaf(w[u], v[u].z, acc.z);
                acc.w = fmaf(w[u], v[u].w, acc.w);
            }
        }
        for (; k < deg; k++) {
            int   j = sj[wrp][k];
            float w = sw[wrp][k];
            float4 v = *(const float4*)&g_Wh[j * OUT_F + col];
            acc.x = fmaf(w, v.x, acc.x); acc.y = fmaf(w, v.y, acc.y);
            acc.z = fmaf(w, v.z, acc.z); acc.w = fmaf(w, v.w, acc.w);
        }

        float inv = 1.0f / ls;
        float4 r;
        r.x = elu1(acc.x * inv);
        r.y = elu1(acc.y * inv);
        r.z = elu1(acc.z * inv);
        r.w = elu1(acc.w * inv);
        *(float4*)&out[i * OUT_F + col] = r;
        return;
    }

    if (deg == 0) {
        float4 acc = make_float4(0.f, 0.f, 0.f, 0.f);
        for (int j = 0; j < NN; j++) {
            float4 v = *(const float4*)&g_Wh[j * OUT_F + col];
            acc.x += v.x; acc.y += v.y; acc.z += v.z; acc.w += v.w;
        }
        const float inv = 1.0f / (float)NN;
        float4 r;
        r.x = elu1(acc.x * inv);
        r.y = elu1(acc.y * inv);
        r.z = elu1(acc.z * inv);
        r.w = elu1(acc.w * inv);
        *(float4*)&out[i * OUT_F + col] = r;
        return;
    }

    // fallback: deg > MAXDEG, bitmask scan (safety net)
    const unsigned* adj = &g_adj[i * ADJ_WORDS_PER_ROW];

    float lmax = -INFINITY;
    for (int base = 0; base < NN; base += 32) {
        unsigned word = adj[base >> 5];
        if (word == 0u) continue;
        if ((word >> lane) & 1u) {
            int j = base + lane;
            float t = s1i + g_s2[j] + batt;
            float e = (t > 0.0f) ? t : ALPHA * t;
            lmax = fmaxf(lmax, e);
        }
    }
#pragma unroll
    for (int o = 16; o > 0; o >>= 1)
        lmax = fmaxf(lmax, __shfl_xor_sync(FULL, lmax, o));

    float4 acc = make_float4(0.f, 0.f, 0.f, 0.f);
    float sumw = 0.0f;
    for (int base = 0; base < NN; base += 32) {
        unsigned word = adj[base >> 5];
        bool present = (word >> lane) & 1u;
        float wl = 0.0f;
        if (present) {
            int j = base + lane;
            float t = s1i + g_s2[j] + batt;
            float e = (t > 0.0f) ? t : ALPHA * t;
            wl = __expf(e - lmax);
            sumw += wl;
        }
        unsigned mask = word;
        while (mask) {
            int b = __ffs(mask) - 1;
            mask &= mask - 1;
            float w = __shfl_sync(FULL, wl, b);
            int j = base + b;
            float4 v = *(const float4*)&g_Wh[j * OUT_F + col];
            acc.x = fmaf(w, v.x, acc.x); acc.y = fmaf(w, v.y, acc.y);
            acc.z = fmaf(w, v.z, acc.z); acc.w = fmaf(w, v.w, acc.w);
        }
    }
#pragma unroll
    for (int o = 16; o > 0; o >>= 1)
        sumw += __shfl_xor_sync(FULL, sumw, o);

    float inv = 1.0f / sumw;
    float4 r;
    r.x = elu1(acc.x * inv);
    r.y = elu1(acc.y * inv);
    r.z = elu1(acc.z * inv);
    r.w = elu1(acc.w * inv);
    *(float4*)&out[i * OUT_F + col] = r;
}

// ---------------------------------------------------------------------------
// Launch
// ---------------------------------------------------------------------------
extern "C" void kernel_launch(void* const* d_in, const int* in_sizes, int n_in,
                              void* d_out, int out_size) {
    const float* h     = (const float*)d_in[0];
    const int*   ei    = (const int*)d_in[1];
    const float* W     = (const float*)d_in[2];
    const float* b_lin = (const float*)d_in[3];
    const float* a     = (const float*)d_in[4];
    const float* b_att = (const float*)d_in[5];
    float* out = (float*)d_out;

    int E = in_sizes[1] / 2;

    {
        int total = (NN * ADJ_WORDS_PER_ROW) / 4;
        zero_adj_kernel<<<(total + 255) / 256, 256>>>();
    }
    scatter_kernel<<<(E + 255) / 256, 256>>>(ei, E);
    gemm_s_kernel<<<NN / 32, 256>>>(h, W, b_lin, a);
    attn_kernel<<<NN / 8, 256>>>(b_att, out);
}

// round 12
// speedup vs baseline: 1.2356x; 1.2356x over previous
#include <cuda_runtime.h>
#include <cuda_bf16.h>
#include <math.h>

// Problem constants
#define NN     8192
#define IN_F   256
#define OUT_F  128
#define ALPHA  0.2f

#define ADJ_WORDS_PER_ROW (NN / 32)   // 256
#define MAXDEG 128

// Scratch (device globals; no allocation)
__device__ unsigned g_adj[NN * ADJ_WORDS_PER_ROW];   // 8 MB bitmask (dedup + fallback)
__device__ int      g_deg[NN];                       // deduped degree
__device__ int      g_nbr[NN * MAXDEG];              // neighbor lists (4 MB)
__device__ float    g_Wh[NN * OUT_F];                // 4 MB
__device__ float    g_s1[NN];
__device__ float    g_s2[NN];

// ---- f32x2 helpers -----------------------------------------------------
__device__ __forceinline__ void upk2(unsigned long long v, float& lo, float& hi) {
    asm("mov.b64 {%0, %1}, %2;" : "=f"(lo), "=f"(hi) : "l"(v));
}
#define FMA2(acc, a, b) \
    asm("fma.rn.f32x2 %0, %1, %2, %0;" : "+l"(acc) : "l"(a), "l"(b))

// ---------------------------------------------------------------------------
// Kernel 1: zero adjacency bitmask + degree array
// ---------------------------------------------------------------------------
__global__ __launch_bounds__(256) void zero_adj_kernel() {
    int idx = blockIdx.x * blockDim.x + threadIdx.x;      // uint4 index
    const int total = (NN * ADJ_WORDS_PER_ROW) / 4;       // 524288
    if (idx < total) {
        ((uint4*)g_adj)[idx] = make_uint4(0u, 0u, 0u, 0u);
    }
    if (idx < NN) g_deg[idx] = 0;
}

// ---------------------------------------------------------------------------
// Kernel 2: scatter edges; bitmask atomicOr dedups, unique edges appended.
// ---------------------------------------------------------------------------
__global__ __launch_bounds__(256) void scatter_kernel(const int* __restrict__ edge_index,
                                                      int E) {
    int k = blockIdx.x * blockDim.x + threadIdx.x;
    if (k < E) {
        int src = edge_index[k]     & (NN - 1);
        int dst = edge_index[E + k] & (NN - 1);
        unsigned bit = 1u << (dst & 31);
        unsigned old = atomicOr(&g_adj[src * ADJ_WORDS_PER_ROW + (dst >> 5)], bit);
        if (!(old & bit)) {
            int pos = atomicAdd(&g_deg[src], 1);
            if (pos < MAXDEG) g_nbr[src * MAXDEG + pos] = dst;
        }
    }
}

// ---------------------------------------------------------------------------
// Kernel 3: Wh = h @ W^T + b_lin (fused s1/s2), FFMA2 with COLUMN pairs.
// Block = 128 threads = 4 warps; BM=32 rows/block -> grid 256.
// Warp tr owns rows [tr*8, tr*8+8); lane owns cols [tc*4, tc*4+4).
// B in normal transposed layout ws[k][n]: one LDS.128 = 2 free f32x2 operands.
// A stored DUPLICATED as float2 (h,h): one LDS.128 broadcast = 2 rows' pairs.
// acc[r][p]: r=row 0..7, p=colpair 0..1; lo=col 2p, hi=col 2p+1.
// ---------------------------------------------------------------------------
__global__ __launch_bounds__(128) void gemm_s_kernel(const float* __restrict__ h,
                                                     const float* __restrict__ W,
                                                     const float* __restrict__ b_lin,
                                                     const float* __restrict__ a) {
    const int BM = 32, BK = 32;
    __shared__ float2 hs2[BK][BM];       // 8 KB  : duplicated (h,h) pairs
    __shared__ float  ws[BK][OUT_F];     // 16 KB : ws[k][n], normal layout

    int row0 = blockIdx.x * BM;
    int tid  = threadIdx.x;
    int tr   = tid >> 5;   // warp 0..3 -> rows tr*8..tr*8+7
    int tc   = tid & 31;   // lane -> cols tc*4..tc*4+3

    unsigned long long acc[8][2];
#pragma unroll
    for (int r = 0; r < 8; r++) { acc[r][0] = 0ull; acc[r][1] = 0ull; }

    for (int k0 = 0; k0 < IN_F; k0 += BK) {
        // --- h tile: 32x32 floats, 2 float4 per thread, store duplicated ---
#pragma unroll
        for (int l = 0; l < 2; l++) {
            int idx = tid + 128 * l;         // 0..255
            int m   = idx >> 3;              // 0..31
            int kq  = idx & 7;
            float4 v = *(const float4*)&h[(row0 + m) * IN_F + k0 + kq * 4];
            hs2[kq * 4 + 0][m] = make_float2(v.x, v.x);
            hs2[kq * 4 + 1][m] = make_float2(v.y, v.y);
            hs2[kq * 4 + 2][m] = make_float2(v.z, v.z);
            hs2[kq * 4 + 3][m] = make_float2(v.w, v.w);
        }
        // --- W tile: 128x32 floats, 8 float4 per thread, transposed ---
#pragma unroll
        for (int l = 0; l < 8; l++) {
            int idx = tid + 128 * l;         // 0..1023
            int n   = idx >> 3;              // 0..127
            int kq  = idx & 7;
            float4 v = *(const float4*)&W[n * IN_F + k0 + kq * 4];
            ws[kq * 4 + 0][n] = v.x;
            ws[kq * 4 + 1][n] = v.y;
            ws[kq * 4 + 2][n] = v.z;
            ws[kq * 4 + 3][n] = v.w;
        }
        __syncthreads();

#pragma unroll
        for (int k = 0; k < BK; k++) {
            // b pairs: (b0,b1) and (b2,b3) straight from one LDS.128
            ulonglong2 bv = *(const ulonglong2*)&ws[k][tc * 4];
            unsigned long long b01 = bv.x, b23 = bv.y;
#pragma unroll
            for (int rp = 0; rp < 4; rp++) {
                // broadcast: rows (tr*8+2rp, tr*8+2rp+1) duplicated pairs
                ulonglong2 av = *(const ulonglong2*)&hs2[k][tr * 8 + rp * 2];
                FMA2(acc[rp * 2 + 0][0], av.x, b01);
                FMA2(acc[rp * 2 + 0][1], av.x, b23);
                FMA2(acc[rp * 2 + 1][0], av.y, b01);
                FMA2(acc[rp * 2 + 1][1], av.y, b23);
            }
        }
        __syncthreads();
    }

    // epilogue: unpack, bias, store Wh, fused s1/s2
    int col = tc * 4;
    float4 blv = *(const float4*)&b_lin[col];
    float4 a1v = *(const float4*)&a[col];
    float4 a2v = *(const float4*)&a[OUT_F + col];

#pragma unroll
    for (int i = 0; i < 8; i++) {
        int row = row0 + tr * 8 + i;
        float c0, c1, c2, c3;
        upk2(acc[i][0], c0, c1);
        upk2(acc[i][1], c2, c3);
        float v0 = c0 + blv.x;
        float v1 = c1 + blv.y;
        float v2 = c2 + blv.z;
        float v3 = c3 + blv.w;
        *(float4*)&g_Wh[row * OUT_F + col] = make_float4(v0, v1, v2, v3);
        float p1 = v0 * a1v.x + v1 * a1v.y + v2 * a1v.z + v3 * a1v.w;
        float p2 = v0 * a2v.x + v1 * a2v.y + v2 * a2v.z + v3 * a2v.w;
#pragma unroll
        for (int o = 16; o > 0; o >>= 1) {
            p1 += __shfl_xor_sync(0xffffffffu, p1, o);
            p2 += __shfl_xor_sync(0xffffffffu, p2, o);
        }
        if (tc == 0) {
            g_s1[row] = p1;
            g_s2[row] = p2;
        }
    }
}

// ---------------------------------------------------------------------------
// Kernel 4: warp-per-row softmax + aggregation + ELU (8-deep gather unroll)
// ---------------------------------------------------------------------------
__device__ __forceinline__ float elu1(float v) {
    return (v > 0.0f) ? v : expm1f(v);
}

__global__ __launch_bounds__(256) void attn_kernel(const float* __restrict__ b_att_p,
                                                   float* __restrict__ out) {
    __shared__ int   sj[8][MAXDEG];
    __shared__ float sw[8][MAXDEG];

    const unsigned FULL = 0xffffffffu;
    int lane = threadIdx.x & 31;
    int wrp  = threadIdx.x >> 5;
    int i    = blockIdx.x * 8 + wrp;

    float batt = *b_att_p;
    float s1i  = g_s1[i];
    int   deg  = g_deg[i];
    int   col  = lane * 4;

    if (deg > 0 && deg <= MAXDEG) {
        const int* nbr = &g_nbr[i * MAXDEG];

        int   jarr[4];
        float earr[4];
        float lmax = -INFINITY;
#pragma unroll
        for (int c = 0; c < 4; c++) {
            int k = c * 32 + lane;
            if (k < deg) {
                int j = nbr[k];
                float t = s1i + g_s2[j] + batt;
                float e = (t > 0.0f) ? t : ALPHA * t;
                jarr[c] = j;
                earr[c] = e;
                lmax = fmaxf(lmax, e);
            }
        }
#pragma unroll
        for (int o = 16; o > 0; o >>= 1)
            lmax = fmaxf(lmax, __shfl_xor_sync(FULL, lmax, o));

        float ls = 0.0f;
#pragma unroll
        for (int c = 0; c < 4; c++) {
            int k = c * 32 + lane;
            if (k < deg) {
                float w = __expf(earr[c] - lmax);
                sj[wrp][k] = jarr[c];
                sw[wrp][k] = w;
                ls += w;
            }
        }
#pragma unroll
        for (int o = 16; o > 0; o >>= 1)
            ls += __shfl_xor_sync(FULL, ls, o);
        __syncwarp();

        // aggregation: 8 gathers in flight
        float4 acc = make_float4(0.f, 0.f, 0.f, 0.f);
        int k = 0;
        for (; k + 8 <= deg; k += 8) {
            float4 v[8];
            float  w[8];
#pragma unroll
            for (int u = 0; u < 8; u++) {
                int j = sj[wrp][k + u];
                w[u]  = sw[wrp][k + u];
                v[u]  = *(const float4*)&g_Wh[j * OUT_F + col];
            }
#pragma unroll
            for (int u = 0; u < 8; u++) {
                acc.x = fmaf(w[u], v[u].x, acc.x);
                acc.y = fmaf(w[u], v[u].y, acc.y);
                acc.z = fmaf(w[u], v[u].z, acc.z);
                acc.w = fmaf(w[u], v[u].w, acc.w);
            }
        }
        for (; k < deg; k++) {
            int   j = sj[wrp][k];
            float w = sw[wrp][k];
            float4 v = *(const float4*)&g_Wh[j * OUT_F + col];
            acc.x = fmaf(w, v.x, acc.x); acc.y = fmaf(w, v.y, acc.y);
            acc.z = fmaf(w, v.z, acc.z); acc.w = fmaf(w, v.w, acc.w);
        }

        float inv = 1.0f / ls;
        float4 r;
        r.x = elu1(acc.x * inv);
        r.y = elu1(acc.y * inv);
        r.z = elu1(acc.z * inv);
        r.w = elu1(acc.w * inv);
        *(float4*)&out[i * OUT_F + col] = r;
        return;
    }

    if (deg == 0) {
        float4 acc = make_float4(0.f, 0.f, 0.f, 0.f);
        for (int j = 0; j < NN; j++) {
            float4 v = *(const float4*)&g_Wh[j * OUT_F + col];
            acc.x += v.x; acc.y += v.y; acc.z += v.z; acc.w += v.w;
        }
        const float inv = 1.0f / (float)NN;
        float4 r;
        r.x = elu1(acc.x * inv);
        r.y = elu1(acc.y * inv);
        r.z = elu1(acc.z * inv);
        r.w = elu1(acc.w * inv);
        *(float4*)&out[i * OUT_F + col] = r;
        return;
    }

    // fallback: deg > MAXDEG, bitmask scan (safety net)
    const unsigned* adj = &g_adj[i * ADJ_WORDS_PER_ROW];

    float lmax = -INFINITY;
    for (int base = 0; base < NN; base += 32) {
        unsigned word = adj[base >> 5];
        if (word == 0u) continue;
        if ((word >> lane) & 1u) {
            int j = base + lane;
            float t = s1i + g_s2[j] + batt;
            float e = (t > 0.0f) ? t : ALPHA * t;
            lmax = fmaxf(lmax, e);
        }
    }
#pragma unroll
    for (int o = 16; o > 0; o >>= 1)
        lmax = fmaxf(lmax, __shfl_xor_sync(FULL, lmax, o));

    float4 acc = make_float4(0.f, 0.f, 0.f, 0.f);
    float sumw = 0.0f;
    for (int base = 0; base < NN; base += 32) {
        unsigned word = adj[base >> 5];
        bool present = (word >> lane) & 1u;
        float wl = 0.0f;
        if (present) {
            int j = base + lane;
            float t = s1i + g_s2[j] + batt;
            float e = (t > 0.0f) ? t : ALPHA * t;
            wl = __expf(e - lmax);
            sumw += wl;
        }
        unsigned mask = word;
        while (mask) {
            int b = __ffs(mask) - 1;
            mask &= mask - 1;
            float w = __shfl_sync(FULL, wl, b);
            int j = base + b;
            float4 v = *(const float4*)&g_Wh[j * OUT_F + col];
            acc.x = fmaf(w, v.x, acc.x); acc.y = fmaf(w, v.y, acc.y);
            acc.z = fmaf(w, v.z, acc.z); acc.w = fmaf(w, v.w, acc.w);
        }
    }
#pragma unroll
    for (int o = 16; o > 0; o >>= 1)
        sumw += __shfl_xor_sync(FULL, sumw, o);

    float inv = 1.0f / sumw;
    float4 r;
    r.x = elu1(acc.x * inv);
    r.y = elu1(acc.y * inv);
    r.z = elu1(acc.z * inv);
    r.w = elu1(acc.w * inv);
    *(float4*)&out[i * OUT_F + col] = r;
}

// ---------------------------------------------------------------------------
// Launch
// ---------------------------------------------------------------------------
extern "C" void kernel_launch(void* const* d_in, const int* in_sizes, int n_in,
                              void* d_out, int out_size) {
    const float* h     = (const float*)d_in[0];
    const int*   ei    = (const int*)d_in[1];
    const float* W     = (const float*)d_in[2];
    const float* b_lin = (const float*)d_in[3];
    const float* a     = (const float*)d_in[4];
    const float* b_att = (const float*)d_in[5];
    float* out = (float*)d_out;

    int E = in_sizes[1] / 2;

    {
        int total = (NN * ADJ_WORDS_PER_ROW) / 4;
        zero_adj_kernel<<<(total + 255) / 256, 256>>>();
    }
    scatter_kernel<<<(E + 255) / 256, 256>>>(ei, E);
    gemm_s_kernel<<<NN / 32, 128>>>(h, W, b_lin, a);
    attn_kernel<<<NN / 8, 256>>>(b_att, out);
}

// round 17
// speedup vs baseline: 1.3084x; 1.0589x over previous
#include <cuda_runtime.h>
#include <cuda_bf16.h>
#include <math.h>

// Problem constants
#define NN     8192
#define IN_F   256
#define OUT_F  128
#define ALPHA  0.2f

#define ADJ_WORDS_PER_ROW (NN / 32)   // 256
#define MAXDEG 128

// Scratch (device globals; no allocation)
__device__ unsigned g_adj[NN * ADJ_WORDS_PER_ROW];   // 8 MB bitmask (dedup + fallback)
__device__ int      g_deg[NN];                       // deduped degree
__device__ int      g_nbr[NN * MAXDEG];              // neighbor lists (4 MB)
__device__ float    g_Wh[NN * OUT_F];                // 4 MB
__device__ float    g_s1[NN];
__device__ float    g_s2[NN];

// ---------------------------------------------------------------------------
// Kernel 1: zero adjacency bitmask + degree array
// ---------------------------------------------------------------------------
__global__ __launch_bounds__(256) void zero_adj_kernel() {
    int idx = blockIdx.x * blockDim.x + threadIdx.x;      // uint4 index
    const int total = (NN * ADJ_WORDS_PER_ROW) / 4;       // 524288
    if (idx < total) {
        ((uint4*)g_adj)[idx] = make_uint4(0u, 0u, 0u, 0u);
    }
    if (idx < NN) g_deg[idx] = 0;
}

// ---------------------------------------------------------------------------
// Kernel 2: scatter edges; bitmask atomicOr dedups, unique edges appended.
// ---------------------------------------------------------------------------
__global__ __launch_bounds__(256) void scatter_kernel(const int* __restrict__ edge_index,
                                                      int E) {
    int k = blockIdx.x * blockDim.x + threadIdx.x;
    if (k < E) {
        int src = edge_index[k]     & (NN - 1);
        int dst = edge_index[E + k] & (NN - 1);
        unsigned bit = 1u << (dst & 31);
        unsigned old = atomicOr(&g_adj[src * ADJ_WORDS_PER_ROW + (dst >> 5)], bit);
        if (!(old & bit)) {
            int pos = atomicAdd(&g_deg[src], 1);
            if (pos < MAXDEG) g_nbr[src * MAXDEG + pos] = dst;
        }
    }
}

// ---------------------------------------------------------------------------
// Kernel 3: Wh = h @ W^T + b_lin (fused s1/s2 epilogue), scalar FFMA.
// R2's proven per-thread structure (8 rows x 4 cols, 3x LDS.128 + 32 FFMA/k),
// but BM=32 with 128 threads -> grid 256 (~2 blocks/SM) for occupancy.
// Warp tr (0..3) owns rows [tr*8, tr*8+8); lane tc owns cols [tc*4, tc*4+4).
// ---------------------------------------------------------------------------
__global__ __launch_bounds__(128) void gemm_s_kernel(const float* __restrict__ h,
                                                     const float* __restrict__ W,
                                                     const float* __restrict__ b_lin,
                                                     const float* __restrict__ a) {
    const int BM = 32, BK = 32;
    __shared__ float hs[BK][BM];       // 4 KB  : hs[k][m]
    __shared__ float ws[BK][OUT_F];    // 16 KB : ws[k][n]

    int row0 = blockIdx.x * BM;
    int tid  = threadIdx.x;
    int tr   = tid >> 5;   // warp id 0..3 -> rows tr*8..tr*8+7
    int tc   = tid & 31;   // lane -> cols tc*4..tc*4+3

    float acc[8][4];
#pragma unroll
    for (int i = 0; i < 8; i++)
#pragma unroll
        for (int j = 0; j < 4; j++) acc[i][j] = 0.0f;

    for (int k0 = 0; k0 < IN_F; k0 += BK) {
        // h tile: 32x32 floats = 256 float4, 2 per thread
#pragma unroll
        for (int l = 0; l < 2; l++) {
            int idx = tid + 128 * l;          // 0..255
            int m   = idx >> 3;               // 0..31
            int kq  = idx & 7;
            float4 v = *(const float4*)&h[(row0 + m) * IN_F + k0 + kq * 4];
            hs[kq * 4 + 0][m] = v.x;
            hs[kq * 4 + 1][m] = v.y;
            hs[kq * 4 + 2][m] = v.z;
            hs[kq * 4 + 3][m] = v.w;
        }
        // W tile: 128x32 floats = 1024 float4, 8 per thread
#pragma unroll
        for (int l = 0; l < 8; l++) {
            int idx = tid + 128 * l;          // 0..1023
            int n   = idx >> 3;               // 0..127
            int kq  = idx & 7;
            float4 v = *(const float4*)&W[n * IN_F + k0 + kq * 4];
            ws[kq * 4 + 0][n] = v.x;
            ws[kq * 4 + 1][n] = v.y;
            ws[kq * 4 + 2][n] = v.z;
            ws[kq * 4 + 3][n] = v.w;
        }
        __syncthreads();

#pragma unroll
        for (int k = 0; k < BK; k++) {
            float4 ha = *(const float4*)&hs[k][tr * 8];
            float4 hb = *(const float4*)&hs[k][tr * 8 + 4];
            float4 wb = *(const float4*)&ws[k][tc * 4];
            float ra[8] = {ha.x, ha.y, ha.z, ha.w, hb.x, hb.y, hb.z, hb.w};
            float rb[4] = {wb.x, wb.y, wb.z, wb.w};
#pragma unroll
            for (int i = 0; i < 8; i++)
#pragma unroll
                for (int j = 0; j < 4; j++)
                    acc[i][j] = fmaf(ra[i], rb[j], acc[i][j]);
        }
        __syncthreads();
    }

    // epilogue: bias, store Wh, fused s1/s2
    int col = tc * 4;
    float4 blv = *(const float4*)&b_lin[col];
    float4 a1v = *(const float4*)&a[col];
    float4 a2v = *(const float4*)&a[OUT_F + col];

#pragma unroll
    for (int i = 0; i < 8; i++) {
        int row = row0 + tr * 8 + i;
        float v0 = acc[i][0] + blv.x;
        float v1 = acc[i][1] + blv.y;
        float v2 = acc[i][2] + blv.z;
        float v3 = acc[i][3] + blv.w;
        *(float4*)&g_Wh[row * OUT_F + col] = make_float4(v0, v1, v2, v3);
        float p1 = v0 * a1v.x + v1 * a1v.y + v2 * a1v.z + v3 * a1v.w;
        float p2 = v0 * a2v.x + v1 * a2v.y + v2 * a2v.z + v3 * a2v.w;
#pragma unroll
        for (int o = 16; o > 0; o >>= 1) {
            p1 += __shfl_xor_sync(0xffffffffu, p1, o);
            p2 += __shfl_xor_sync(0xffffffffu, p2, o);
        }
        if (tc == 0) {
            g_s1[row] = p1;
            g_s2[row] = p2;
        }
    }
}

// ---------------------------------------------------------------------------
// Kernel 4: warp-per-row softmax + aggregation + ELU (8-deep gather unroll)
// ---------------------------------------------------------------------------
__device__ __forceinline__ float elu1(float v) {
    return (v > 0.0f) ? v : expm1f(v);
}

__global__ __launch_bounds__(256) void attn_kernel(const float* __restrict__ b_att_p,
                                                   float* __restrict__ out) {
    __shared__ int   sj[8][MAXDEG];
    __shared__ float sw[8][MAXDEG];

    const unsigned FULL = 0xffffffffu;
    int lane = threadIdx.x & 31;
    int wrp  = threadIdx.x >> 5;
    int i    = blockIdx.x * 8 + wrp;

    float batt = *b_att_p;
    float s1i  = g_s1[i];
    int   deg  = g_deg[i];
    int   col  = lane * 4;

    if (deg > 0 && deg <= MAXDEG) {
        const int* nbr = &g_nbr[i * MAXDEG];

        int   jarr[4];
        float earr[4];
        float lmax = -INFINITY;
#pragma unroll
        for (int c = 0; c < 4; c++) {
            int k = c * 32 + lane;
            if (k < deg) {
                int j = nbr[k];
                float t = s1i + g_s2[j] + batt;
                float e = (t > 0.0f) ? t : ALPHA * t;
                jarr[c] = j;
                earr[c] = e;
                lmax = fmaxf(lmax, e);
            }
        }
#pragma unroll
        for (int o = 16; o > 0; o >>= 1)
            lmax = fmaxf(lmax, __shfl_xor_sync(FULL, lmax, o));

        float ls = 0.0f;
#pragma unroll
        for (int c = 0; c < 4; c++) {
            int k = c * 32 + lane;
            if (k < deg) {
                float w = __expf(earr[c] - lmax);
                sj[wrp][k] = jarr[c];
                sw[wrp][k] = w;
                ls += w;
            }
        }
#pragma unroll
        for (int o = 16; o > 0; o >>= 1)
            ls += __shfl_xor_sync(FULL, ls, o);
        __syncwarp();

        // aggregation: 8 gathers in flight
        float4 acc = make_float4(0.f, 0.f, 0.f, 0.f);
        int k = 0;
        for (; k + 8 <= deg; k += 8) {
            float4 v[8];
            float  w[8];
#pragma unroll
            for (int u = 0; u < 8; u++) {
                int j = sj[wrp][k + u];
                w[u]  = sw[wrp][k + u];
                v[u]  = *(const float4*)&g_Wh[j * OUT_F + col];
            }
#pragma unroll
            for (int u = 0; u < 8; u++) {
                acc.x = fmaf(w[u], v[u].x, acc.x);
                acc.y = fmaf(w[u], v[u].y, acc.y);
                acc.z = fmaf(w[u], v[u].z, acc.z);
                acc.w = fmaf(w[u], v[u].w, acc.w);
            }
        }
        for (; k < deg; k++) {
            int   j = sj[wrp][k];
            float w = sw[wrp][k];
            float4 v = *(const float4*)&g_Wh[j * OUT_F + col];
            acc.x = fmaf(w, v.x, acc.x); acc.y = fmaf(w, v.y, acc.y);
            acc.z = fmaf(w, v.z, acc.z); acc.w = fmaf(w, v.w, acc.w);
        }

        float inv = 1.0f / ls;
        float4 r;
        r.x = elu1(acc.x * inv);
        r.y = elu1(acc.y * inv);
        r.z = elu1(acc.z * inv);
        r.w = elu1(acc.w * inv);
        *(float4*)&out[i * OUT_F + col] = r;
        return;
    }

    if (deg == 0) {
        float4 acc = make_float4(0.f, 0.f, 0.f, 0.f);
        for (int j = 0; j < NN; j++) {
            float4 v = *(const float4*)&g_Wh[j * OUT_F + col];
            acc.x += v.x; acc.y += v.y; acc.z += v.z; acc.w += v.w;
        }
        const float inv = 1.0f / (float)NN;
        float4 r;
        r.x = elu1(acc.x * inv);
        r.y = elu1(acc.y * inv);
        r.z = elu1(acc.z * inv);
        r.w = elu1(acc.w * inv);
        *(float4*)&out[i * OUT_F + col] = r;
        return;
    }

    // fallback: deg > MAXDEG, bitmask scan (safety net)
    const unsigned* adj = &g_adj[i * ADJ_WORDS_PER_ROW];

    float lmax = -INFINITY;
    for (int base = 0; base < NN; base += 32) {
        unsigned word = adj[base >> 5];
        if (word == 0u) continue;
        if ((word >> lane) & 1u) {
            int j = base + lane;
            float t = s1i + g_s2[j] + batt;
            float e = (t > 0.0f) ? t : ALPHA * t;
            lmax = fmaxf(lmax, e);
        }
    }
#pragma unroll
    for (int o = 16; o > 0; o >>= 1)
        lmax = fmaxf(lmax, __shfl_xor_sync(FULL, lmax, o));

    float4 acc = make_float4(0.f, 0.f, 0.f, 0.f);
    float sumw = 0.0f;
    for (int base = 0; base < NN; base += 32) {
        unsigned word = adj[base >> 5];
        bool present = (word >> lane) & 1u;
        float wl = 0.0f;
        if (present) {
            int j = base + lane;
            float t = s1i + g_s2[j] + batt;
            float e = (t > 0.0f) ? t : ALPHA * t;
            wl = __expf(e - lmax);
            sumw += wl;
        }
        unsigned mask = word;
        while (mask) {
            int b = __ffs(mask) - 1;
            mask &= mask - 1;
            float w = __shfl_sync(FULL, wl, b);
            int j = base + b;
            float4 v = *(const float4*)&g_Wh[j * OUT_F + col];
            acc.x = fmaf(w, v.x, acc.x); acc.y = fmaf(w, v.y, acc.y);
            acc.z = fmaf(w, v.z, acc.z); acc.w = fmaf(w, v.w, acc.w);
        }
    }
#pragma unroll
    for (int o = 16; o > 0; o >>= 1)
        sumw += __shfl_xor_sync(FULL, sumw, o);

    float inv = 1.0f / sumw;
    float4 r;
    r.x = elu1(acc.x * inv);
    r.y = elu1(acc.y * inv);
    r.z = elu1(acc.z * inv);
    r.w = elu1(acc.w * inv);
    *(float4*)&out[i * OUT_F + col] = r;
}

// ---------------------------------------------------------------------------
// Launch
// ---------------------------------------------------------------------------
extern "C" void kernel_launch(void* const* d_in, const int* in_sizes, int n_in,
                              void* d_out, int out_size) {
    const float* h     = (const float*)d_in[0];
    const int*   ei    = (const int*)d_in[1];
    const float* W     = (const float*)d_in[2];
    const float* b_lin = (const float*)d_in[3];
    const float* a     = (const float*)d_in[4];
    const float* b_att = (const float*)d_in[5];
    float* out = (float*)d_out;

    int E = in_sizes[1] / 2;

    {
        int total = (NN * ADJ_WORDS_PER_ROW) / 4;
        zero_adj_kernel<<<(total + 255) / 256, 256>>>();
    }
    scatter_kernel<<<(E + 255) / 256, 256>>>(ei, E);
    gemm_s_kernel<<<NN / 32, 128>>>(h, W, b_lin, a);
    attn_kernel<<<NN / 8, 256>>>(b_att, out);
}